// round 8
// baseline (speedup 1.0000x reference)
#include <cuda_runtime.h>
#include <cstdint>

#define N_PTS   16384
#define GRIDD   32
#define CELLS   (GRIDD * GRIDD * GRIDD)
#define LOF     (-5.0f)
#define CELL    0.3125f
#define INVCELL 3.2f
#define SUBQ    4
#define BIGF    1.0e30f

// Scratch in device globals. Invariants restored every call:
//  g_cnt == 0 at count_kernel entry (load-time zero; scan restores),
//  g_rcount == 0 at reduce entry (load-time zero; last block restores).
__device__ int      g_cnt[2][CELLS];
__device__ int      g_start[2][CELLS + 8];
__device__ unsigned g_cidrank[2][N_PTS];   // (cid << 17) | rank, unsigned
__device__ float4   g_pts[2][N_PTS];       // cell-sorted: (x, y, z, |p|^2)
__device__ float    g_sq[2][N_PTS];        // sqrt(min sq dist) per query
__device__ float    g_partial[8];
__device__ int      g_rcount;

__device__ __forceinline__ int cell_coord(float v) {
    int c = (int)((v - LOF) * INVCELL);
    return min(max(c, 0), GRIDD - 1);
}

__global__ void count_kernel(const float* __restrict__ sx,
                             const float* __restrict__ tg) {
    int idx = blockIdx.x * blockDim.x + threadIdx.x;
    int cl = idx >> 14, i = idx & (N_PTS - 1);
    const float* p = cl ? tg : sx;
    float x = p[3 * i], y = p[3 * i + 1], z = p[3 * i + 2];
    int cid = (cell_coord(z) << 10) | (cell_coord(y) << 5) | cell_coord(x);
    unsigned rank = (unsigned)atomicAdd(&g_cnt[cl][cid], 1);
    g_cidrank[cl][i] = ((unsigned)cid << 17) | rank;
}

__global__ __launch_bounds__(1024) void scan_kernel() {
    __shared__ int sh[1024];
    const int cl = blockIdx.x;
    const int t = threadIdx.x;
    int4* c4 = (int4*)&g_cnt[cl][0];
    int loc[32];
    int sum = 0;
    #pragma unroll
    for (int k = 0; k < 8; k++) {
        int4 v = c4[t * 8 + k];
        loc[4*k+0] = v.x; loc[4*k+1] = v.y; loc[4*k+2] = v.z; loc[4*k+3] = v.w;
        sum += (v.x + v.y) + (v.z + v.w);
        c4[t * 8 + k] = make_int4(0, 0, 0, 0);   // restore invariant
    }
    sh[t] = sum;
    __syncthreads();
    for (int off = 1; off < 1024; off <<= 1) {   // Hillis-Steele inclusive
        int v = (t >= off) ? sh[t - off] : 0;
        __syncthreads();
        sh[t] += v;
        __syncthreads();
    }
    int run = sh[t] - sum;                        // exclusive prefix
    int4* s4 = (int4*)&g_start[cl][0];
    #pragma unroll
    for (int k = 0; k < 8; k++) {
        int4 w;
        w.x = run; run += loc[4*k+0];
        w.y = run; run += loc[4*k+1];
        w.z = run; run += loc[4*k+2];
        w.w = run; run += loc[4*k+3];
        s4[t * 8 + k] = w;
    }
    if (t == 1023) g_start[cl][CELLS] = run;      // == N_PTS
}

__global__ void scatter_kernel(const float* __restrict__ sx,
                               const float* __restrict__ tg) {
    int idx = blockIdx.x * blockDim.x + threadIdx.x;
    int cl = idx >> 14, i = idx & (N_PTS - 1);
    const float* p = cl ? tg : sx;
    float x = p[3 * i], y = p[3 * i + 1], z = p[3 * i + 2];
    unsigned cr = g_cidrank[cl][i];
    int pos = g_start[cl][cr >> 17] + (int)(cr & 0x1FFFFu);
    g_pts[cl][pos] = make_float4(x, y, z, x * x + y * y + z * z);
}

// One query per 4-thread quad; branch-free 3x3x3 fast path with a tight
// geometric resolution bound; rare unresolved queries finished by the
// whole warp with a bounded two-phase scan (no iterative cube rescans).
__global__ __launch_bounds__(256, 4) void search_kernel() {
    const int gtid = blockIdx.x * 256 + threadIdx.x;
    const int qcl = blockIdx.y;
    const int rcl = qcl ^ 1;
    const int qid = gtid >> 2;
    const int sub = gtid & 3;
    const int lane = threadIdx.x & 31;
    const unsigned qmask = 0xFu << (threadIdx.x & 28);

    const float4 q = g_pts[qcl][qid];
    const float nax = -2.0f * q.x, nay = -2.0f * q.y, naz = -2.0f * q.z;
    const int cx = cell_coord(q.x), cy = cell_coord(q.y), cz = cell_coord(q.z);

    const float4* __restrict__ ref = g_pts[rcl];
    const int* __restrict__ st = g_start[rcl];

    // ---- fast path: 3x3x3 neighborhood as 9 contiguous x-row ranges ----
    const int xlo = max(cx - 1, 0), xhi = min(cx + 1, GRIDD - 1);
    const int ylo = max(cy - 1, 0), yhi = min(cy + 1, GRIDD - 1);
    const int zlo = max(cz - 1, 0), zhi = min(cz + 1, GRIDD - 1);
    int zr[3] = {zlo, cz, zhi};
    int yr[3] = {ylo, cy, yhi};

    int s9[9], e9[9];
    #pragma unroll
    for (int i = 0; i < 9; i++) {
        int row = (zr[i / 3] << 10) | (yr[i % 3] << 5);
        s9[i] = st[row + xlo];
        e9[i] = st[row + xhi + 1];
    }

    float m = BIGF * BIGF;   // acts as +inf, stays finite through fma
    #pragma unroll
    for (int i = 0; i < 9; i++) {
        int p = s9[i] + sub;
        const int e = e9[i];
        for (; p + SUBQ < e; p += 2 * SUBQ) {
            float4 t0 = ref[p];
            float4 t1 = ref[p + SUBQ];
            float d0 = fmaf(nax, t0.x, fmaf(nay, t0.y, fmaf(naz, t0.z, t0.w)));
            float d1 = fmaf(nax, t1.x, fmaf(nay, t1.y, fmaf(naz, t1.z, t1.w)));
            m = fminf(m, fminf(d0, d1));
        }
        if (p < e) {
            float4 t = ref[p];
            m = fminf(m, fmaf(nax, t.x, fmaf(nay, t.y, fmaf(naz, t.z, t.w))));
        }
    }
    m = fminf(m, __shfl_xor_sync(qmask, m, 1));
    m = fminf(m, __shfl_xor_sync(qmask, m, 2));
    float best = fmaxf(q.w + m, 0.0f);

    // Tight resolution bound: true distance from the query point to each
    // face of the scanned slab [xlo, xhi]x[ylo, yhi]x[zlo, zhi]. Faces at
    // the grid edge are infinite (all points are clamped inside the grid).
    float bnd = BIGF;
    if (xlo > 0)        bnd = fminf(bnd, q.x - (LOF + (float)xlo * CELL));
    if (xhi < GRIDD-1)  bnd = fminf(bnd, (LOF + (float)(xhi+1) * CELL) - q.x);
    if (ylo > 0)        bnd = fminf(bnd, q.y - (LOF + (float)ylo * CELL));
    if (yhi < GRIDD-1)  bnd = fminf(bnd, (LOF + (float)(yhi+1) * CELL) - q.y);
    if (zlo > 0)        bnd = fminf(bnd, q.z - (LOF + (float)zlo * CELL));
    if (zhi < GRIDD-1)  bnd = fminf(bnd, (LOF + (float)(zhi+1) * CELL) - q.z);

    bool unresolved = best > bnd * bnd;
    unsigned pmask = __ballot_sync(0xFFFFFFFFu, unresolved && sub == 0);
    if (sub == 0 && !unresolved) g_sq[qcl][qid] = sqrtf(best);

    // ---- rare path: whole warp finishes each pending query together ----
    while (pmask) {
        const int src = __ffs(pmask) - 1;
        pmask &= pmask - 1;
        const float bqx = __shfl_sync(0xFFFFFFFFu, q.x, src);
        const float bqy = __shfl_sync(0xFFFFFFFFu, q.y, src);
        const float bqz = __shfl_sync(0xFFFFFFFFu, q.z, src);
        const float bqw = __shfl_sync(0xFFFFFFFFu, q.w, src);
        float mm = __shfl_sync(0xFFFFFFFFu, m, src);
        const float bax = -2.0f * bqx, bay = -2.0f * bqy, baz = -2.0f * bqz;
        const int bcx = cell_coord(bqx), bcy = cell_coord(bqy),
                  bcz = cell_coord(bqz);

        // Phase 1: expand cube radius until ANY point is seen (mm finite).
        // Rows lane-striped; empty rows cost only two loads.
        for (int r = 2; mm >= BIGF && r <= GRIDD; r++) {
            int x0 = max(bcx - r, 0), x1 = min(bcx + r, GRIDD - 1);
            int y0 = max(bcy - r, 0), y1 = min(bcy + r, GRIDD - 1);
            int z0 = max(bcz - r, 0), z1 = min(bcz + r, GRIDD - 1);
            int ny = y1 - y0 + 1;
            int nrows = (z1 - z0 + 1) * ny;
            for (int rr = lane; rr < nrows; rr += 32) {
                int zz = z0 + rr / ny;
                int yy = y0 + rr % ny;
                int row = (zz << 10) | (yy << 5);
                int s = st[row + x0], e = st[row + x1 + 1];
                for (int p = s; p < e; p++) {
                    float4 t = ref[p];
                    mm = fminf(mm, fmaf(bax, t.x,
                               fmaf(bay, t.y, fmaf(baz, t.z, t.w))));
                }
            }
            #pragma unroll
            for (int o = 16; o; o >>= 1)
                mm = fminf(mm, __shfl_xor_sync(0xFFFFFFFFu, mm, o));
        }

        // Phase 2: one bounded cube pass. Upper bound dub = sqrt(best_ub);
        // cells with Chebyshev > R hold points >= R*CELL >= dub away.
        float dub = sqrtf(fmaxf(bqw + mm, 0.0f));
        int R = min((int)ceilf(dub * INVCELL), GRIDD);
        {
            int x0 = max(bcx - R, 0), x1 = min(bcx + R, GRIDD - 1);
            int y0 = max(bcy - R, 0), y1 = min(bcy + R, GRIDD - 1);
            int z0 = max(bcz - R, 0), z1 = min(bcz + R, GRIDD - 1);
            int ny = y1 - y0 + 1;
            int nrows = (z1 - z0 + 1) * ny;
            for (int rr = lane; rr < nrows; rr += 32) {
                int zz = z0 + rr / ny;
                int yy = y0 + rr % ny;
                int row = (zz << 10) | (yy << 5);
                int s = st[row + x0], e = st[row + x1 + 1];
                for (int p = s; p < e; p++) {
                    float4 t = ref[p];
                    mm = fminf(mm, fmaf(bax, t.x,
                               fmaf(bay, t.y, fmaf(baz, t.z, t.w))));
                }
            }
            #pragma unroll
            for (int o = 16; o; o >>= 1)
                mm = fminf(mm, __shfl_xor_sync(0xFFFFFFFFu, mm, o));
        }
        if (lane == src) g_sq[qcl][qid] = sqrtf(fmaxf(bqw + mm, 0.0f));
    }
}

__global__ __launch_bounds__(1024) void reduce_kernel(float* __restrict__ out) {
    __shared__ float red[1024];
    const int tid = threadIdx.x;
    const float4* v = (const float4*)g_sq;        // 8192 float4 total
    float4 t = v[blockIdx.x * 1024 + tid];
    red[tid] = (t.x + t.y) + (t.z + t.w);
    __syncthreads();
    #pragma unroll
    for (int off = 512; off > 0; off >>= 1) {
        if (tid < off) red[tid] += red[tid + off];
        __syncthreads();
    }
    if (tid == 0) {
        g_partial[blockIdx.x] = red[0];
        __threadfence();
        if (atomicAdd(&g_rcount, 1) == 7) {       // last block finishes
            float s = 0.0f;
            volatile float* gp = g_partial;
            #pragma unroll
            for (int i = 0; i < 8; i++) s += gp[i];  // fixed order
            out[0] = s * (5.0f / (float)N_PTS);   // (mean1 + mean2)*0.5*10
            g_rcount = 0;                          // restore invariant
        }
    }
}

extern "C" void kernel_launch(void* const* d_in, const int* in_sizes, int n_in,
                              void* d_out, int out_size) {
    const float* state_x = (const float*)d_in[0];
    const float* target  = (const float*)d_in[1];

    count_kernel<<<(2 * N_PTS) / 256, 256>>>(state_x, target);
    scan_kernel<<<2, 1024>>>();
    scatter_kernel<<<(2 * N_PTS) / 256, 256>>>(state_x, target);

    dim3 sgrid((N_PTS * SUBQ) / 256, 2);
    search_kernel<<<sgrid, 256>>>();

    reduce_kernel<<<8, 1024>>>((float*)d_out);
}